// round 8
// baseline (speedup 1.0000x reference)
#include <cuda_runtime.h>
#include <cuda_fp16.h>
#include <math.h>

#define FEAT 32
#define NA 64
#define NE 32
#define NL 33           // elevation levels L = 0..NE ; quad(L) = levels (L, L+1) incl. poles
#define WARPS 4
#define BLK 128

// Quad table: for azimuth edge al (columns al, al+1 mod NA) and level q:
// g_quad[((al*NL+q)*32 + f)] = {left.lo, left.hi, right.lo, right.hi} = 8 bytes.
// One (al,q) column = 32 * 8B = 256B.
__device__ __half2 g_quad[NA * NL * FEAT * 2];
__device__ float g_ticks_az[NA];
__device__ float g_ticks_el[NE];
__device__ float g_consts[4];  // inv_so_az, inv_so_el, omega_az, omega_el

__global__ void prep_kernel(const float* __restrict__ grid,
                            const float* __restrict__ poles) {
    int idx = blockIdx.x * blockDim.x + threadIdx.x;
    if (idx == 0) {
        double oaz = 2.0 * M_PI / (double)NA;
        double oel = M_PI / (double)(NE + 1);
        g_consts[0] = (float)(1.0 / sin(oaz));
        g_consts[1] = (float)(1.0 / sin(oel));
        g_consts[2] = (float)oaz;
        g_consts[3] = (float)oel;
    }
    if (idx < NA)
        g_ticks_az[idx] = (float)((double)idx * (2.0 * M_PI / (double)NA) - M_PI);
    if (idx < NE)
        g_ticks_el[idx] = (float)((double)(idx + 1) * (M_PI / (double)(NE + 1)) - M_PI / 2.0);
    if (idx < NA * NL * FEAT) {
        int f = idx & 31;
        int c = idx >> 5;
        int q = c % NL;
        int al = c / NL;
        int ar = (al + 1) & (NA - 1);
        float xl = (q == 0)  ? poles[2 * f]     : grid[(((f << 6) + al) << 5) + (q - 1)];
        float yl = (q == NE) ? poles[2 * f + 1] : grid[(((f << 6) + al) << 5) + q];
        float xr = (q == 0)  ? poles[2 * f]     : grid[(((f << 6) + ar) << 5) + (q - 1)];
        float yr = (q == NE) ? poles[2 * f + 1] : grid[(((f << 6) + ar) << 5) + q];
        g_quad[2 * idx]     = __floats2half2_rn(xl, yl);
        g_quad[2 * idx + 1] = __floats2half2_rn(xr, yr);
    }
}

__global__ void __launch_bounds__(BLK, 9)
interp_kernel(const float* __restrict__ pts,
              float* __restrict__ out, int n) {
    __shared__ float  s_ta[NA];
    __shared__ float  s_te[NE];
    __shared__ float  s_c[4];
    __shared__ float4 s_rec[WARPS][32];       // {cf0 | off in low 12 mantissa bits, cf1, cf2, cf3}
    __shared__ float  s_tile[WARPS][32][36];  // point-major [p][f], stride 36

    const int t    = threadIdx.x;
    const int warp = t >> 5;
    const int lane = t & 31;

    if (t < NA) s_ta[t] = g_ticks_az[t];
    if (t < NE) s_te[t] = g_ticks_el[t];
    if (t < 4)  s_c[t]  = g_consts[t];
    __syncthreads();

    const int base = blockIdx.x * BLK + warp * 32;

    // ---------- Phase 1: per-lane point -> packed record in smem ------------
    {
        int ip = base + lane;
        int ic = min(ip, n - 1);
        float az = pts[ic];
        float el = pts[n + ic];

        const float inv_so_az = s_c[0];
        const float inv_so_el = s_c[1];
        const float omega_az  = s_c[2];
        const float omega_el  = s_c[3];

        // azimuth searchsorted(side='left')
        int r = (int)((az + 3.14159274101257324f) / omega_az);
        r = min(max(r, 0), NA);
        while (r < NA && s_ta[r] < az) ++r;
        while (r > 0 && s_ta[r - 1] >= az) --r;
        int al = (r - 1 < 0) ? (NA - 1) : (r - 1);   // ar == (al+1) mod NA always
        float theta_a = az - s_ta[al];
        float w1a = __sinf(omega_az - theta_a) * inv_so_az;
        float w2a = __sinf(theta_a) * inv_so_az;

        // elevation searchsorted -> level q in [0, NE]
        int q = (int)((el + 1.57079637050628662f) / omega_el);
        q = min(max(q, 0), NE);
        while (q < NE && s_te[q] < el) ++q;
        while (q > 0 && s_te[q - 1] >= el) --q;
        bool south = (q == 0);
        bool north = (q == NE);
        float bse = south ? -1.57079632679489662f : s_te[q - 1];
        float theta_e = el - bse;
        float w1e = __sinf(omega_el - theta_e) * inv_so_el;
        float w2e = __sinf(theta_e) * inv_so_el;

        // pole rows appear in BOTH azimuth columns -> renormalize that weight
        float s  = w1a + w2a;
        float wx = south ? __fdividef(w1e, s) : w1e;
        float wy = north ? __fdividef(w2e, s) : w2e;

        float cf0 = wx * w1a;
        // steal low 12 mantissa bits of cf0 for the column index (0..2111)
        unsigned col  = (unsigned)(al * NL + q);
        unsigned bits = (__float_as_uint(cf0) & ~0xFFFu) | col;
        s_rec[warp][lane] = make_float4(__uint_as_float(bits),
                                        wy * w1a, wx * w2a, wy * w2a);
    }
    __syncwarp();

    // ---------- Phase 2: warp-cooperative gather (lane = feature) -----------
    const char* __restrict__ gq = (const char*)g_quad;

#pragma unroll 4
    for (int p = 0; p < 32; ++p) {
        float4 rec = s_rec[warp][p];                     // 1 broadcast LDS.128
        unsigned bits = __float_as_uint(rec.x);
        unsigned off  = (bits & 0xFFFu) << 8;            // 256B per column
        float cf0 = __uint_as_float(bits & ~0xFFFu);
        uint2 q2 = *(const uint2*)(gq + off + 8 * lane); // single LDG.64
        float2 fl = __half22float2(*(const __half2*)&q2.x);
        float2 fr = __half22float2(*(const __half2*)&q2.y);
        float res = cf0 * fl.x;
        res = fmaf(rec.y, fl.y, res);
        res = fmaf(rec.z, fr.x, res);
        res = fmaf(rec.w, fr.y, res);
        s_tile[warp][p][lane] = res;   // banks (4p+lane)%32 distinct: conflict-free
    }
    __syncwarp();

    // ---------- Phase 3: per-lane LDS.128 (aligned, conflict-free) + STG ----
    int ip = base + lane;
    if (ip < n) {
        float* o = out + ip;
        const size_t sn = (size_t)n;
#pragma unroll
        for (int j = 0; j < 8; ++j) {
            float4 v = *(const float4*)&s_tile[warp][lane][4 * j];
            o[0] = v.x; o += sn;
            o[0] = v.y; o += sn;
            o[0] = v.z; o += sn;
            o[0] = v.w; o += sn;
        }
    }
}

extern "C" void kernel_launch(void* const* d_in, const int* in_sizes, int n_in,
                              void* d_out, int out_size) {
    const float* pts   = (const float*)d_in[0];  // (2, N)
    const float* grid  = (const float*)d_in[1];  // (32, 64, 32)
    const float* poles = (const float*)d_in[2];  // (32, 2)
    float* out = (float*)d_out;                  // (32, N)
    int n = in_sizes[0] / 2;

    prep_kernel<<<(NA * NL * FEAT + 255) / 256, 256>>>(grid, poles);
    interp_kernel<<<(n + BLK - 1) / BLK, BLK>>>(pts, out, n);
}

// round 9
// speedup vs baseline: 1.5222x; 1.5222x over previous
#include <cuda_runtime.h>
#include <cuda_fp16.h>
#include <math.h>

#define FEAT 32
#define NA 64
#define NE 32
#define NL 33           // elevation levels L = 0..NE ; quad(L) = levels (L, L+1) incl. poles
#define WARPS 4
#define BLK 128

// Quad table: for azimuth edge al (columns al, al+1 mod NA) and level q:
// g_quad[2*((al*NL+q)*32 + f)] = left pair {v[L],v[L+1]}, [..+1] = right pair. 8B per feature.
// One (al,q) column = 32 * 8B = 256B.
__device__ __half2 g_quad[NA * NL * FEAT * 2];
__device__ float g_ticks_az[NA];
__device__ float g_ticks_el[NE];
__device__ float g_consts[4];  // inv_so_az, inv_so_el, omega_az, omega_el

__global__ void prep_kernel(const float* __restrict__ grid,
                            const float* __restrict__ poles) {
    int idx = blockIdx.x * blockDim.x + threadIdx.x;
    if (idx == 0) {
        double oaz = 2.0 * M_PI / (double)NA;
        double oel = M_PI / (double)(NE + 1);
        g_consts[0] = (float)(1.0 / sin(oaz));
        g_consts[1] = (float)(1.0 / sin(oel));
        g_consts[2] = (float)oaz;
        g_consts[3] = (float)oel;
    }
    if (idx < NA)
        g_ticks_az[idx] = (float)((double)idx * (2.0 * M_PI / (double)NA) - M_PI);
    if (idx < NE)
        g_ticks_el[idx] = (float)((double)(idx + 1) * (M_PI / (double)(NE + 1)) - M_PI / 2.0);
    if (idx < NA * NL * FEAT) {
        int f = idx & 31;
        int c = idx >> 5;
        int q = c % NL;
        int al = c / NL;
        int ar = (al + 1) & (NA - 1);
        float xl = (q == 0)  ? poles[2 * f]     : grid[(((f << 6) + al) << 5) + (q - 1)];
        float yl = (q == NE) ? poles[2 * f + 1] : grid[(((f << 6) + al) << 5) + q];
        float xr = (q == 0)  ? poles[2 * f]     : grid[(((f << 6) + ar) << 5) + (q - 1)];
        float yr = (q == NE) ? poles[2 * f + 1] : grid[(((f << 6) + ar) << 5) + q];
        g_quad[2 * idx]     = __floats2half2_rn(xl, yl);
        g_quad[2 * idx + 1] = __floats2half2_rn(xr, yr);
    }
}

__global__ void __launch_bounds__(BLK, 8)
interp_kernel(const float* __restrict__ pts,
              float* __restrict__ out, int n) {
    __shared__ float  s_ta[NA];
    __shared__ float  s_te[NE];
    __shared__ float  s_c[4];
    __shared__ float4 s_cf[WARPS][32];        // 4 bilinear coeffs (fp32)
    __shared__ float  s_tile[WARPS][32][36];  // point-major [p][f], stride 36

    const int t    = threadIdx.x;
    const int warp = t >> 5;
    const int lane = t & 31;

    if (t < NA) s_ta[t] = g_ticks_az[t];
    if (t < NE) s_te[t] = g_ticks_el[t];
    if (t < 4)  s_c[t]  = g_consts[t];
    __syncthreads();

    const int base = blockIdx.x * BLK + warp * 32;

    // ---------- Phase 1: per-lane point -> 4 coeffs (smem) + offset (reg) ----
    unsigned my_off;
    {
        int ip = base + lane;
        int ic = min(ip, n - 1);
        float az = pts[ic];
        float el = pts[n + ic];

        const float inv_so_az = s_c[0];
        const float inv_so_el = s_c[1];
        const float omega_az  = s_c[2];
        const float omega_el  = s_c[3];

        // azimuth searchsorted(side='left')
        int r = (int)((az + 3.14159274101257324f) / omega_az);
        r = min(max(r, 0), NA);
        while (r < NA && s_ta[r] < az) ++r;
        while (r > 0 && s_ta[r - 1] >= az) --r;
        int al = (r - 1 < 0) ? (NA - 1) : (r - 1);   // ar == (al+1) mod NA always
        float theta_a = az - s_ta[al];
        float w1a = __sinf(omega_az - theta_a) * inv_so_az;
        float w2a = __sinf(theta_a) * inv_so_az;

        // elevation searchsorted -> level q in [0, NE]
        int q = (int)((el + 1.57079637050628662f) / omega_el);
        q = min(max(q, 0), NE);
        while (q < NE && s_te[q] < el) ++q;
        while (q > 0 && s_te[q - 1] >= el) --q;
        bool south = (q == 0);
        bool north = (q == NE);
        float bse = south ? -1.57079632679489662f : s_te[q - 1];
        float theta_e = el - bse;
        float w1e = __sinf(omega_el - theta_e) * inv_so_el;
        float w2e = __sinf(theta_e) * inv_so_el;

        // pole rows appear in BOTH azimuth columns -> renormalize that weight
        float s  = w1a + w2a;
        float wx = south ? __fdividef(w1e, s) : w1e;
        float wy = north ? __fdividef(w2e, s) : w2e;

        s_cf[warp][lane] = make_float4(wx * w1a, wy * w1a, wx * w2a, wy * w2a);
        my_off = (unsigned)(al * NL + q) << 8;   // byte offset of 256B column
    }
    __syncwarp();

    // ---------- Phase 2: 2 points / iteration; lane covers 2 features -------
    // lanes 0-15 -> point 2i, lanes 16-31 -> point 2i+1; lane serves features
    // {2*(lane&15), 2*(lane&15)+1} via one LDG.128.
    const char* __restrict__ gq = (const char*)g_quad;
    const int half = lane >> 4;
    const int fp   = lane & 15;

#pragma unroll 4
    for (int i = 0; i < 16; ++i) {
        int p = 2 * i + half;
        unsigned off = __shfl_sync(0xffffffffu, my_off, p);
        float4 cf = s_cf[warp][p];                        // 2 addrs/warp: 1 instr
        uint4 q4 = *(const uint4*)(gq + off + 16 * fp);   // single LDG.128
        float2 l0 = __half22float2(*(const __half2*)&q4.x);
        float2 r0 = __half22float2(*(const __half2*)&q4.y);
        float2 l1 = __half22float2(*(const __half2*)&q4.z);
        float2 r1 = __half22float2(*(const __half2*)&q4.w);
        float res0 = cf.x * l0.x;
        res0 = fmaf(cf.y, l0.y, res0);
        res0 = fmaf(cf.z, r0.x, res0);
        res0 = fmaf(cf.w, r0.y, res0);
        float res1 = cf.x * l1.x;
        res1 = fmaf(cf.y, l1.y, res1);
        res1 = fmaf(cf.z, r1.x, res1);
        res1 = fmaf(cf.w, r1.y, res1);
        // STS.64; per half-warp banks 2*fp(+const) all distinct: conflict-free
        *(float2*)&s_tile[warp][p][2 * fp] = make_float2(res0, res1);
    }
    __syncwarp();

    // ---------- Phase 3: per-lane LDS.128 (aligned, conflict-free) + STG ----
    int ip = base + lane;
    if (ip < n) {
        float* o = out + ip;
        const size_t sn = (size_t)n;
#pragma unroll
        for (int j = 0; j < 8; ++j) {
            float4 v = *(const float4*)&s_tile[warp][lane][4 * j];
            o[0] = v.x; o += sn;
            o[0] = v.y; o += sn;
            o[0] = v.z; o += sn;
            o[0] = v.w; o += sn;
        }
    }
}

extern "C" void kernel_launch(void* const* d_in, const int* in_sizes, int n_in,
                              void* d_out, int out_size) {
    const float* pts   = (const float*)d_in[0];  // (2, N)
    const float* grid  = (const float*)d_in[1];  // (32, 64, 32)
    const float* poles = (const float*)d_in[2];  // (32, 2)
    float* out = (float*)d_out;                  // (32, N)
    int n = in_sizes[0] / 2;

    prep_kernel<<<(NA * NL * FEAT + 255) / 256, 256>>>(grid, poles);
    interp_kernel<<<(n + BLK - 1) / BLK, BLK>>>(pts, out, n);
}